// round 15
// baseline (speedup 1.0000x reference)
#include <cuda_runtime.h>
#include <math.h>
#include <stdint.h>

// Multiresolution hash-grid encoding, spatially-sorted gather (v5).
//
//  K1 hist    : Morton bucket (res 32); atomicAdd rank; packed key store
//  K2 scan    : exclusive scan -> bucket bases; restores g_hist zeros
//  K3 scatter : pos = base+rank (no atomics); plain float4 store
//  K4 main    : one thread per sorted point. 16-level loop, x-pair float4
//               hash merge with WEIGHT-SWAP formulation (parity folded into
//               x-weights: 2 SEL/group instead of ~6, e-term zeroed when
//               unused). Output staged in padded smem, warp-transposed
//               stores (4 wavefronts per STG.128 instead of 32).

#define N_LEVELS 16
#define LOG2_T   19
#define T_MASK   ((1u << LOG2_T) - 1u)
#define P1       2654435761u
#define P2       805459861u

#define SORT_RES   32
#define N_BUCKETS  (SORT_RES * SORT_RES * SORT_RES)   // 2^15
#define MAX_N      1100000

#define TPB       256
#define ROW_PAD   9          // float4 units per smem row (8 data + 1 pad)

__device__ unsigned g_hist[N_BUCKETS];   // zero-init; scan restores zeros
__device__ unsigned g_base[N_BUCKETS];
__device__ unsigned g_key[MAX_N];        // bucket | rank<<15
__device__ float4   g_xs[MAX_N];         // sorted (x,y,z, idx-as-bits)

struct Params { float resf[N_LEVELS]; };

// ------------------------------------------------------------------ morton
__device__ __forceinline__ unsigned expand_bits(unsigned v) {
    v = (v * 0x00010001u) & 0xFF0000FFu;
    v = (v * 0x00000101u) & 0x0F00F00Fu;
    v = (v * 0x00000011u) & 0xC30C30C3u;
    v = (v * 0x00000005u) & 0x49249249u;
    return v;
}

__device__ __forceinline__ unsigned bucket_of(float px, float py, float pz) {
    int cx = (int)(px * (float)SORT_RES);
    int cy = (int)(py * (float)SORT_RES);
    int cz = (int)(pz * (float)SORT_RES);
    cx = min(max(cx, 0), SORT_RES - 1);
    cy = min(max(cy, 0), SORT_RES - 1);
    cz = min(max(cz, 0), SORT_RES - 1);
    return expand_bits((unsigned)cx)
         | (expand_bits((unsigned)cy) << 1)
         | (expand_bits((unsigned)cz) << 2);
}

// ---------------------------------------------------------------- kernels
__global__ __launch_bounds__(TPB) void hist_kernel(const float* __restrict__ x, int N) {
    int n = blockIdx.x * TPB + threadIdx.x;
    if (n >= N) return;
    unsigned b = bucket_of(x[n * 3 + 0], x[n * 3 + 1], x[n * 3 + 2]);
    unsigned r = atomicAdd(&g_hist[b], 1u);
    g_key[n] = b | (r << 15);
}

__global__ __launch_bounds__(1024) void scan_kernel() {
    __shared__ unsigned partial[1024];
    const int t = threadIdx.x;
    unsigned local[32];
    unsigned s = 0;
    #pragma unroll
    for (int j = 0; j < 32; ++j) {
        local[j] = g_hist[t * 32 + j];
        g_hist[t * 32 + j] = 0u;        // restore zero-invariant
        s += local[j];
    }
    partial[t] = s;
    __syncthreads();
    for (int d = 1; d < 1024; d <<= 1) {
        unsigned v = (t >= d) ? partial[t - d] : 0u;
        __syncthreads();
        partial[t] += v;
        __syncthreads();
    }
    unsigned run = (t > 0) ? partial[t - 1] : 0u;
    #pragma unroll
    for (int j = 0; j < 32; ++j) { g_base[t * 32 + j] = run; run += local[j]; }
}

__global__ __launch_bounds__(TPB) void scatter_kernel(const float* __restrict__ x, int N) {
    int n = blockIdx.x * TPB + threadIdx.x;
    if (n >= N) return;
    const unsigned k = __ldcs(&g_key[n]);                 // read-once stream
    const unsigned pos = g_base[k & (N_BUCKETS - 1)] + (k >> 15);
    g_xs[pos] = make_float4(x[n * 3 + 0], x[n * 3 + 1], x[n * 3 + 2],
                            __int_as_float(n));
}

// ------------------------------------------------------------------- main
__global__ __launch_bounds__(TPB, 5) void hashgrid_kernel(
    const float2* __restrict__ table,   // [T] float2
    float4* __restrict__ out,           // [N,8] float4 rows
    Params p, int N)
{
    __shared__ float4 s_row[TPB * ROW_PAD];   // 36 KB
    __shared__ int    s_n[TPB];

    const int tid  = threadIdx.x;
    const int lane = tid & 31;
    const int i = blockIdx.x * TPB + tid;
    const bool valid = (i < N);

    int n = -1;
    if (valid) {
        const float4 xi = __ldcs(&g_xs[i]);   // read-once: keep L1 for table
        const float px = xi.x, py = xi.y, pz = xi.z;
        n = __float_as_int(xi.w);

        #pragma unroll
        for (int l = 0; l < N_LEVELS; l += 2) {
            float2 pr[2];
            #pragma unroll
            for (int s = 0; s < 2; ++s) {
                const float res = p.resf[l + s];
                const float sx = px * res;
                const float sy = py * res;
                const float sz = pz * res;

                const float fx = floorf(sx);
                const float fy = floorf(sy);
                const float fz = floorf(sz);

                const float dx = sx - fx;
                const float dy = sy - fy;
                const float dz = sz - fz;

                const unsigned x0u = (unsigned)(int)fx;
                const unsigned hy0 = (unsigned)(int)fy * P1;
                const unsigned hy1 = hy0 + P1;
                const unsigned hz0 = (unsigned)(int)fz * P2;
                const unsigned hz1 = hz0 + P2;

                const unsigned g00 = hy0 ^ hz0;
                const unsigned g10 = hy1 ^ hz0;
                const unsigned g01 = hy0 ^ hz1;
                const unsigned g11 = hy1 ^ hz1;

                const unsigned h000 = (x0u ^ g00) & T_MASK;
                const unsigned h010 = (x0u ^ g10) & T_MASK;
                const unsigned h001 = (x0u ^ g01) & T_MASK;
                const unsigned h011 = (x0u ^ g11) & T_MASK;

                const bool xeven = (x0u & 1u) == 0u;

                // 4 float4 loads: always hold the x0 corner at parity
                // position; when x0 even the other half is the x1 corner.
                const float4 q00 = __ldg((const float4*)&table[h000 & ~1u]);
                const float4 q10 = __ldg((const float4*)&table[h010 & ~1u]);
                const float4 q01 = __ldg((const float4*)&table[h001 & ~1u]);
                const float4 q11 = __ldg((const float4*)&table[h011 & ~1u]);

                // odd-x0 extra gathers (x1 corners); zeroed otherwise so the
                // e*cw term is exactly 0 (cw=0 when even).
                float2 e00 = make_float2(0.f, 0.f), e10 = make_float2(0.f, 0.f);
                float2 e01 = make_float2(0.f, 0.f), e11 = make_float2(0.f, 0.f);
                if (!xeven) {
                    const unsigned x1u = x0u + 1u;
                    e00 = __ldg(&table[(x1u ^ g00) & T_MASK]);
                    e10 = __ldg(&table[(x1u ^ g10) & T_MASK]);
                    e01 = __ldg(&table[(x1u ^ g01) & T_MASK]);
                    e11 = __ldg(&table[(x1u ^ g11) & T_MASK]);
                }

                const float wx0 = 1.0f - dx, wx1 = dx;
                const float wy0 = 1.0f - dy, wy1 = dy;
                const float wz0 = 1.0f - dz, wz1 = dz;

                // weight-swap: fold parity & evenness into x-weights.
                //  even,p=0: lo*wx0 + hi*wx1          even,p=1: lo*wx1 + hi*wx0
                //  odd, p=0: lo*wx0 + e*wx1           odd, p=1: hi*wx0 + e*wx1
                const float t  = xeven ? wx1 : 0.0f;
                const float cw = xeven ? 0.0f : wx1;

                const bool p00 = (h000 & 1u), p10 = (h010 & 1u),
                           p01 = (h001 & 1u), p11 = (h011 & 1u);

                const float a00 = p00 ? t : wx0, b00 = p00 ? wx0 : t;
                const float a10 = p10 ? t : wx0, b10 = p10 ? wx0 : t;
                const float a01 = p01 ? t : wx0, b01 = p01 ? wx0 : t;
                const float a11 = p11 ? t : wx0, b11 = p11 ? wx0 : t;

                const float c00x = q00.x * a00 + q00.z * b00 + e00.x * cw;
                const float c00y = q00.y * a00 + q00.w * b00 + e00.y * cw;
                const float c10x = q10.x * a10 + q10.z * b10 + e10.x * cw;
                const float c10y = q10.y * a10 + q10.w * b10 + e10.y * cw;
                const float c01x = q01.x * a01 + q01.z * b01 + e01.x * cw;
                const float c01y = q01.y * a01 + q01.w * b01 + e01.y * cw;
                const float c11x = q11.x * a11 + q11.z * b11 + e11.x * cw;
                const float c11y = q11.y * a11 + q11.w * b11 + e11.y * cw;

                const float b0x = c00x * wy0 + c10x * wy1;
                const float b0y = c00y * wy0 + c10y * wy1;
                const float b1x = c01x * wy0 + c11x * wy1;
                const float b1y = c01y * wy0 + c11y * wy1;

                pr[s].x = b0x * wz0 + b1x * wz1;
                pr[s].y = b0y * wz0 + b1y * wz1;
            }
            s_row[tid * ROW_PAD + (l >> 1)] =
                make_float4(pr[0].x, pr[0].y, pr[1].x, pr[1].y);
        }
    }
    s_n[tid] = n;
    __syncwarp();

    // Warp transpose store: 4 groups of 8 lanes each write one full 128B
    // output row contiguously -> 4 wavefronts per STG.128.
    const int wbase = tid & ~31;
    const int chunk = lane & 7;
    #pragma unroll
    for (int iter = 0; iter < 8; ++iter) {
        const int row = wbase + iter * 4 + (lane >> 3);
        const int nn = s_n[row];
        if (nn >= 0) {
            __stcs(&out[(size_t)nn * 8 + chunk], s_row[row * ROW_PAD + chunk]);
        }
    }
}

// ----------------------------------------------------------------- launch
extern "C" void kernel_launch(void* const* d_in, const int* in_sizes, int n_in,
                              void* d_out, int out_size)
{
    const float*  x     = (const float*)d_in[0];
    const float2* table = (const float2*)d_in[1];
    float4*       out   = (float4*)d_out;

    const int N = in_sizes[0] / 3;

    Params p;
    {
        const double growth = exp((log(128.0) - log(16.0)) / (double)(N_LEVELS - 1));
        for (int l = 0; l < N_LEVELS; ++l)
            p.resf[l] = (float)floor(16.0 * pow(growth, (double)l));
    }

    const int pb = (N + TPB - 1) / TPB;

    hist_kernel<<<pb, TPB>>>(x, N);
    scan_kernel<<<1, 1024>>>();
    scatter_kernel<<<pb, TPB>>>(x, N);
    hashgrid_kernel<<<pb, TPB>>>(table, out, p, N);
}